// round 12
// baseline (speedup 1.0000x reference)
#include <cuda_runtime.h>
#include <math.h>
#include <stdint.h>

#define BATCH 8
#define LPTS  2048
#define NPTS  (BATCH*LPTS)
#define HIN   20
#define K1    16
#define K2    32
#define NG    32
#define DM    128
#define DH    32
#define PPB   8          // points per stage1 block (256 threads)

__device__ int   g_knn[NPTS * K2];
__device__ float g_heads[NPTS * 8];   // padded to 32B/point for vector access

__device__ __forceinline__ unsigned long long pk2(float lo, float hi) {
    unsigned long long r;
    asm("mov.b64 %0,{%1,%2};" : "=l"(r) : "f"(lo), "f"(hi));
    return r;
}
__device__ __forceinline__ unsigned long long fma2(unsigned long long a,
                                                   unsigned long long b,
                                                   unsigned long long c) {
    unsigned long long d;
    asm("fma.rn.f32x2 %0,%1,%2,%3;" : "=l"(d) : "l"(a), "l"(b), "l"(c));
    return d;
}
__device__ __forceinline__ float upk_sum(unsigned long long v) {
    float lo, hi;
    asm("mov.b64 {%0,%1},%2;" : "=f"(lo), "=f"(hi) : "l"(v));
    return lo + hi;
}

// ---- Kernel A: warp-per-query exact top-32; 2-min summary + bitonic thr ----
__global__ __launch_bounds__(512) void knn_kernel(const float* __restrict__ frames)
{
    __shared__ float4 sc[LPTS];   // x, y, z, |c|^2 (32KB)
    const int t = threadIdx.x;
    const int b  = blockIdx.x >> 7;
    const int l0 = (blockIdx.x & 127) * 16;

    const float* fb = frames + (size_t)b * LPTS * 12;
    for (int j = t; j < LPTS; j += 512) {
        float x = fb[j*12+0], y = fb[j*12+1], z = fb[j*12+2];
        float sq = __fadd_rn(__fadd_rn(__fmul_rn(x,x), __fmul_rn(y,y)), __fmul_rn(z,z));
        sc[j] = make_float4(x, y, z, sq);
    }
    __syncthreads();

    const int w = t >> 5, lane = t & 31;
    const int l = l0 + w;
    const float4 q = sc[l];
    const float xi = q.x, yi = q.y, zi = q.z, sqi = q.w;

    // Pass 1: two smallest keys per lane (64 summary values warp-wide).
    unsigned ka = 0xFFFFFFFFu, kb = 0xFFFFFFFFu;
    #pragma unroll 8
    for (int i = 0; i < 64; i++) {
        const float4 c = sc[i * 32 + lane];
        float dot = __fadd_rn(__fadd_rn(__fmul_rn(xi,c.x), __fmul_rn(yi,c.y)), __fmul_rn(zi,c.z));
        float d2  = __fadd_rn(__fadd_rn(sqi, c.w), __fmul_rn(-2.0f, dot));
        unsigned ub  = __float_as_uint(d2);
        unsigned key = (ub & 0x80000000u) ? ~ub : (ub | 0x80000000u);
        unsigned hi = max(key, ka);
        ka = min(key, ka);
        kb = min(kb, hi);
    }
    // Bitonic sort of 64 summary keys; sorted[31] is a provable upper bound on
    // the global 32nd-smallest key -> tight pass-2 threshold.
    {
        unsigned a = ka, bb = kb;
        #pragma unroll
        for (int k = 2; k <= 64; k <<= 1) {
            #pragma unroll
            for (int j = k >> 1; j > 0; j >>= 1) {
                if (j == 32) {
                    unsigned lo = min(a, bb), hi2 = max(a, bb);
                    a = lo; bb = hi2;
                } else {
                    unsigned oa = __shfl_xor_sync(0xffffffffu, a, j);
                    bool upa = ((lane & j) == 0) == ((lane & k) == 0);
                    a = upa ? min(a, oa) : max(a, oa);
                    unsigned ob = __shfl_xor_sync(0xffffffffu, bb, j);
                    bool upb = ((lane & j) == 0) == (((lane + 32) & k) == 0);
                    bb = upb ? min(bb, ob) : max(bb, ob);
                }
            }
        }
        ka = a;
    }
    unsigned thrk = __shfl_sync(0xffffffffu, ka, 31);

    // Pass 2: prefiltered insertion-select.
    unsigned long long L = ~0ull;
    #pragma unroll 4
    for (int i = 0; i < 64; i++) {
        const int j = i * 32 + lane;
        const float4 c = sc[j];
        float dot = __fadd_rn(__fadd_rn(__fmul_rn(xi,c.x), __fmul_rn(yi,c.y)), __fmul_rn(zi,c.z));
        float d2  = __fadd_rn(__fadd_rn(sqi, c.w), __fmul_rn(-2.0f, dot));
        unsigned ub  = __float_as_uint(d2);
        unsigned key = (ub & 0x80000000u) ? ~ub : (ub | 0x80000000u);
        unsigned long long pk = ((unsigned long long)key << 32) | (unsigned)j;

        unsigned pending = __ballot_sync(0xffffffffu, key <= thrk);
        if (pending) {
            do {
                const int src = __ffs(pending) - 1;
                pending &= pending - 1;
                const unsigned long long v = __shfl_sync(0xffffffffu, pk, src);
                const unsigned lt = __ballot_sync(0xffffffffu, L < v);
                const unsigned long long up = __shfl_up_sync(0xffffffffu, L, 1);
                const int pos = __popc(lt);
                if (lane == pos)      L = v;
                else if (lane > pos)  L = up;
            } while (pending);
            thrk = min(thrk, __shfl_sync(0xffffffffu, (unsigned)(L >> 32), 31));
        }
    }
    g_knn[(size_t)(b * LPTS + l) * K2 + lane] = (int)(L & 0xffffffffu);
}

// ---- Kernel B: fused gaussian conv + M (f32x2) -> 640x128 GEMM -> heads ----
// 8 points / 256 threads so two blocks fit per SM (register file) ->
// cross-block latency hiding through the sync-heavy phases.
__global__ __launch_bounds__(256) void stage1_kernel(
    const float* __restrict__ attr,   const float* __restrict__ frames,
    const int*   __restrict__ aaidx,
    const float* __restrict__ cent1,  const float* __restrict__ prec1,
    const float* __restrict__ opW,    const float* __restrict__ opB,
    const float* __restrict__ embW,   const float* __restrict__ embB,
    const float* __restrict__ betaW,  const float* __restrict__ betaB,
    const float* __restrict__ selfW,  const float* __restrict__ selfB,
    const float* __restrict__ crossW, const float* __restrict__ crossB,
    const float* __restrict__ nodefW, const float* __restrict__ nodefB)
{
    extern __shared__ float sm[];
    float* s_crd  = sm;                       // PPB*16*8   = 1024
    float* s_attr = s_crd  + PPB*16*8;        // PPB*16*20  = 2560
    float* s_M    = s_attr + PPB*16*20;       // PPB*640    = 5120
    float* s_F    = s_M    + PPB*640;         // PPB*128    = 1024

    const int tid  = threadIdx.x;
    const int w    = tid >> 5;
    const int lane = tid & 31;
    const int n    = blockIdx.x * PPB + w;
    const int b    = n >> 11;

    {   // coords (lanes 0..15) / attr gather (lanes 16..31), vectorized
        const int k  = lane & 15;
        const int j  = g_knn[n * K2 + k];
        const int jj = b * LPTS + j;
        if (lane < 16) {
            const float4* fo4 = (const float4*)(frames + (size_t)n * 12);
            float4 f0 = fo4[0], f1 = fo4[1], f2 = fo4[2];
            const float4* fj4 = (const float4*)(frames + (size_t)jj * 12);
            float4 j0 = fj4[0], j2 = fj4[2];
            float dx = j0.x - f0.x, dy = j0.y - f0.y, dz = j0.z - f0.z;
            float dist = sqrtf(dx*dx + dy*dy + dz*dz + 1e-12f);
            float e0 = dx*f0.w + dy*f1.x + dz*f1.y;
            float e1 = dx*f1.z + dy*f1.w + dz*f2.x;
            float e2 = dx*f2.y + dy*f2.z + dz*f2.w;
            float zz  = f2.y*j2.y + f2.z*j2.z + f2.w*j2.w;
            float dzv = (dx*j2.y + dy*j2.z + dz*j2.w) / dist;
            float zdv = (f2.y*dx + f2.z*dy + f2.w*dz) / dist;
            float idist = fminf(fabsf((float)aaidx[jj] - (float)aaidx[n]), 8.0f);
            float* c = s_crd + (w*16 + k) * 8;
            c[0]=e0; c[1]=e1; c[2]=e2; c[3]=idist; c[4]=zz; c[5]=dzv; c[6]=zdv; c[7]=0.f;
        } else {
            const float4* ap = (const float4*)(attr + (size_t)jj * HIN);
            float4* d = (float4*)(s_attr + (w*16 + k) * HIN);
            #pragma unroll
            for (int h = 0; h < 5; h++) d[h] = ap[h];
        }
    }
    __syncwarp();

    {   // fused gaussians (lane = g) + M[g][h] accumulation, f32x2
        unsigned long long pr2[21];
        float pr6[7], ce[7];
        #pragma unroll
        for (int d = 0; d < 7; d++) {
            #pragma unroll
            for (int p = 0; p < 3; p++)
                pr2[d*3+p] = pk2(prec1[(d*7 + 2*p)*NG + lane],
                                 prec1[(d*7 + 2*p + 1)*NG + lane]);
            pr6[d] = prec1[(d*7 + 6)*NG + lane];
            ce[d]  = cent1[d*NG + lane];
        }
        unsigned long long m2[10];
        #pragma unroll
        for (int h = 0; h < 10; h++) m2[h] = 0ull;

        for (int k = 0; k < K1; k++) {
            const float4* cp = (const float4*)(s_crd + (w*16 + k) * 8);
            float4 a = cp[0], bq = cp[1];
            float diff[7] = { a.x-ce[0], a.y-ce[1], a.z-ce[2], a.w-ce[3],
                              bq.x-ce[4], bq.y-ce[5], bq.z-ce[6] };
            unsigned long long y01 = 0ull, y23 = 0ull, y45 = 0ull;
            float y6 = 0.f;
            #pragma unroll
            for (int d = 0; d < 7; d++) {
                unsigned long long dd = pk2(diff[d], diff[d]);
                y01 = fma2(dd, pr2[d*3+0], y01);
                y23 = fma2(dd, pr2[d*3+1], y23);
                y45 = fma2(dd, pr2[d*3+2], y45);
                y6  = fmaf(diff[d], pr6[d], y6);
            }
            unsigned long long acc2 = fma2(y01, y01, fma2(y23, y23, fma2(y45, y45, 0ull)));
            float acc = upk_sum(acc2) + y6*y6;
            float gk = __expf(-0.5f * acc);
            unsigned long long gk2 = pk2(gk, gk);
            const ulonglong2* ap = (const ulonglong2*)(s_attr + (w*16 + k) * HIN);
            #pragma unroll
            for (int qq = 0; qq < 5; qq++) {
                ulonglong2 av = ap[qq];
                m2[qq*2+0] = fma2(gk2, av.x, m2[qq*2+0]);
                m2[qq*2+1] = fma2(gk2, av.y, m2[qq*2+1]);
            }
        }
        unsigned long long* mp = (unsigned long long*)(s_M + w*640 + lane*20);
        #pragma unroll
        for (int h = 0; h < 10; h++) mp[h] = m2[h];
    }
    __syncthreads();

    {   // block GEMM: filt = M(8x640) @ opW(640x128), packed f32x2
        const int o   = tid & 127;
        const int grp = tid >> 7;             // 2 groups x 4 points
        const float* mb = s_M + grp * 4 * 640;
        unsigned long long a0 = 0ull, a1 = 0ull, a2 = 0ull, a3 = 0ull;
        #pragma unroll 4
        for (int gh = 0; gh < 640; gh += 4) {
            ulonglong2 u0 = *(const ulonglong2*)(mb + 0*640 + gh);
            ulonglong2 u1 = *(const ulonglong2*)(mb + 1*640 + gh);
            ulonglong2 u2 = *(const ulonglong2*)(mb + 2*640 + gh);
            ulonglong2 u3 = *(const ulonglong2*)(mb + 3*640 + gh);
            const float* wp = opW + (size_t)gh * DM + o;
            unsigned long long w01 = pk2(wp[0],    wp[DM]);
            unsigned long long w23 = pk2(wp[2*DM], wp[3*DM]);
            a0 = fma2(u0.x, w01, a0); a0 = fma2(u0.y, w23, a0);
            a1 = fma2(u1.x, w01, a1); a1 = fma2(u1.y, w23, a1);
            a2 = fma2(u2.x, w01, a2); a2 = fma2(u2.y, w23, a2);
            a3 = fma2(u3.x, w01, a3); a3 = fma2(u3.y, w23, a3);
        }
        const float bo = opB[o];
        s_F[(grp*4+0)*DM + o] = fmaxf(upk_sum(a0) + bo, 0.f);
        s_F[(grp*4+1)*DM + o] = fmaxf(upk_sum(a1) + bo, 0.f);
        s_F[(grp*4+2)*DM + o] = fmaxf(upk_sum(a2) + bo, 0.f);
        s_F[(grp*4+3)*DM + o] = fmaxf(upk_sum(a3) + bo, 0.f);
    }
    __syncthreads();

    {   // emb (lane = channel) + 5 heads via warp reductions
        float acc = embB[lane];
        const float* fp = s_F + w * DM;
        #pragma unroll
        for (int ob = 0; ob < DM; ob += 4) {
            float4 f = *(const float4*)(fp + ob);
            acc += f.x * embW[(ob+0)*DH + lane];
            acc += f.y * embW[(ob+1)*DH + lane];
            acc += f.z * embW[(ob+2)*DH + lane];
            acc += f.w * embW[(ob+3)*DH + lane];
        }
        float emb = fmaxf(acc, 0.f);
        float hb = emb * betaW[lane];
        float hs = emb * selfW[lane];
        float hc = emb * crossW[lane];
        float h0 = emb * nodefW[lane*2 + 0];
        float h1 = emb * nodefW[lane*2 + 1];
        #pragma unroll
        for (int off = 16; off > 0; off >>= 1) {
            hb += __shfl_xor_sync(0xffffffffu, hb, off);
            hs += __shfl_xor_sync(0xffffffffu, hs, off);
            hc += __shfl_xor_sync(0xffffffffu, hc, off);
            h0 += __shfl_xor_sync(0xffffffffu, h0, off);
            h1 += __shfl_xor_sync(0xffffffffu, h1, off);
        }
        if (lane == 0) {
            float4* hp = (float4*)(g_heads + (size_t)n * 8);
            hp[0] = make_float4(fmaxf(hb + betaB[0],  0.f),
                                fmaxf(hs + selfB[0],  0.f),
                                fmaxf(hc + crossB[0], 0.f),
                                fmaxf(h0 + nodefB[0], 0.f));
            hp[1] = make_float4(fmaxf(h1 + nodefB[1], 0.f), 0.f, 0.f, 0.f);
        }
    }
}

// ---- Kernel C: gaussian attention, packed constants + vector gathers ----
__global__ __launch_bounds__(256) void stage2_kernel(
    const float* __restrict__ frames, const int* __restrict__ aaidx,
    const float* __restrict__ cent2,  const float* __restrict__ prec2,
    const float* __restrict__ emb2W,  const float* __restrict__ emb2B,
    float* __restrict__ out)
{
    __shared__ float s_gau[NG * 32];

    const int tid = threadIdx.x;
    for (int qi = tid; qi < NG * 32; qi += 256) {
        const int n2 = qi >> 5, e = qi & 31;
        float v = 0.f;
        if (e < 20) {
            const int u = e >> 1, d = u >> 1, kk = (u & 1) * 2 + (e & 1);
            v = prec2[(d*5 + kk)*NG + n2];
        } else if (e < 24)  v = cent2[(e-20)*NG + n2];
        else if (e < 28)    v = prec2[((e-24)*5 + 4)*NG + n2];
        else if (e == 28)   v = cent2[4*NG + n2];
        else if (e == 29)   v = prec2[(4*5 + 4)*NG + n2];
        else if (e == 30)   v = emb2W[n2];
        s_gau[qi] = v;
    }
    __syncthreads();

    const int w = tid >> 5, lane = tid & 31;
    const int n = blockIdx.x * 8 + w;
    const int b = n >> 11, l = n & 2047;
    const int j  = g_knn[n * K2 + lane];
    const int jj = b * LPTS + j;

    const float4* fo4 = (const float4*)(frames + (size_t)n * 12);
    float4 f0 = fo4[0], f2 = fo4[2];
    const float4* fj4 = (const float4*)(frames + (size_t)jj * 12);
    float4 j0 = fj4[0], j2 = fj4[2];
    float dx = j0.x - f0.x, dy = j0.y - f0.y, dzc = j0.z - f0.z;
    float dist = sqrtf(dx*dx + dy*dy + dzc*dzc + 1e-12f);
    float zz  = f2.y*j2.y + f2.z*j2.z + f2.w*j2.w;
    float dzv = (dx*j2.y + dy*j2.z + dzc*j2.w) / dist;
    float zdv = (f2.y*dx + f2.z*dy + f2.w*dzc) / dist;
    float idist = fminf(fabsf((float)aaidx[jj] - (float)aaidx[n]), 8.0f);
    const float cd0 = dist, cd1 = zz, cd2 = dzv, cd3 = zdv, cd4 = idist;

    float gw = emb2B[0];
    #pragma unroll 4
    for (int n2 = 0; n2 < NG; n2++) {
        const float* gp = s_gau + n2 * 32;
        const ulonglong2* pp = (const ulonglong2*)gp;
        float4 c03 = *(const float4*)(gp + 20);
        float4 p03 = *(const float4*)(gp + 24);
        float4 tl  = *(const float4*)(gp + 28);
        float df0 = cd0 - c03.x, df1 = cd1 - c03.y, df2 = cd2 - c03.z,
              df3 = cd3 - c03.w, df4 = cd4 - tl.x;
        ulonglong2 q0 = pp[0], q1 = pp[1], q2 = pp[2], q3 = pp[3], q4 = pp[4];
        unsigned long long y01 = 0ull, y23 = 0ull;
        float y4 = 0.f;
        unsigned long long dd;
        dd = pk2(df0, df0); y01 = fma2(dd, q0.x, y01); y23 = fma2(dd, q0.y, y23); y4 = fmaf(df0, p03.x, y4);
        dd = pk2(df1, df1); y01 = fma2(dd, q1.x, y01); y23 = fma2(dd, q1.y, y23); y4 = fmaf(df1, p03.y, y4);
        dd = pk2(df2, df2); y01 = fma2(dd, q2.x, y01); y23 = fma2(dd, q2.y, y23); y4 = fmaf(df2, p03.z, y4);
        dd = pk2(df3, df3); y01 = fma2(dd, q3.x, y01); y23 = fma2(dd, q3.y, y23); y4 = fmaf(df3, p03.w, y4);
        dd = pk2(df4, df4); y01 = fma2(dd, q4.x, y01); y23 = fma2(dd, q4.y, y23); y4 = fmaf(df4, tl.y,  y4);
        unsigned long long acc2 = fma2(y01, y01, fma2(y23, y23, 0ull));
        float acc = upk_sum(acc2) + y4*y4;
        gw += __expf(-0.5f * acc) * tl.z;
    }
    gw = fmaxf(gw, 0.f);

    const float4* hj4 = (const float4*)(g_heads + (size_t)jj * 8);
    float4 ha = hj4[0], hb4 = hj4[1];
    const float* hi = g_heads + (size_t)n * 8;
    float beta = hi[0], satt = hi[1];
    float e = (j == l) ? satt : ha.z;
    float logit = beta * e;
    float mx = logit;
    #pragma unroll
    for (int off = 16; off > 0; off >>= 1)
        mx = fmaxf(mx, __shfl_xor_sync(0xffffffffu, mx, off));
    float wv = gw * __expf(logit - mx);
    float s = wv, n0 = wv * ha.w, n1 = wv * hb4.x;
    #pragma unroll
    for (int off = 16; off > 0; off >>= 1) {
        s  += __shfl_xor_sync(0xffffffffu, s,  off);
        n0 += __shfl_xor_sync(0xffffffffu, n0, off);
        n1 += __shfl_xor_sync(0xffffffffu, n1, off);
    }
    if (lane == 0) {
        float inv = 1.f / (s + 1e-6f);
        out[n*2 + 0] = n0 * inv;
        out[n*2 + 1] = n1 * inv;
    }
}

extern "C" void kernel_launch(void* const* d_in, const int* in_sizes, int n_in,
                              void* d_out, int out_size)
{
    const float* attr    = (const float*)d_in[0];
    const float* frames  = (const float*)d_in[1];
    const int*   aaidx   = (const int*)  d_in[2];
    const float* cent1   = (const float*)d_in[3];
    const float* prec1   = (const float*)d_in[4];
    const float* opW     = (const float*)d_in[5];
    const float* opB     = (const float*)d_in[6];
    const float* embW    = (const float*)d_in[7];
    const float* embB    = (const float*)d_in[8];
    const float* betaW   = (const float*)d_in[9];
    const float* betaB   = (const float*)d_in[10];
    const float* selfW   = (const float*)d_in[11];
    const float* selfB   = (const float*)d_in[12];
    const float* crossW  = (const float*)d_in[13];
    const float* crossB  = (const float*)d_in[14];
    const float* nodefW  = (const float*)d_in[15];
    const float* nodefB  = (const float*)d_in[16];
    const float* cent2   = (const float*)d_in[17];
    const float* prec2   = (const float*)d_in[18];
    const float* emb2W   = (const float*)d_in[19];
    const float* emb2B   = (const float*)d_in[20];
    float* out = (float*)d_out;

    const int smem1 = (PPB*16*8 + PPB*16*20 + PPB*640 + PPB*128) * 4;  // 38912B

    knn_kernel<<<NPTS / 16, 512>>>(frames);
    stage1_kernel<<<NPTS / PPB, 256, smem1>>>(
        attr, frames, aaidx, cent1, prec1, opW, opB, embW, embB,
        betaW, betaB, selfW, selfB, crossW, crossB, nodefW, nodefB);
    stage2_kernel<<<NPTS / 8, 256>>>(frames, aaidx, cent2, prec2, emb2W, emb2B, out);
}

// round 14
// speedup vs baseline: 1.0497x; 1.0497x over previous
#include <cuda_runtime.h>
#include <math.h>
#include <stdint.h>

#define BATCH 8
#define LPTS  2048
#define NPTS  (BATCH*LPTS)
#define HIN   20
#define K1    16
#define K2    32
#define NG    32
#define DM    128
#define DH    32
#define S1P   32          // stage1 points per block

__device__ int   g_knn[NPTS * K2];
__device__ float g_heads[NPTS * 8];

__device__ __forceinline__ unsigned long long pk2(float lo, float hi) {
    unsigned long long r;
    asm("mov.b64 %0,{%1,%2};" : "=l"(r) : "f"(lo), "f"(hi));
    return r;
}
__device__ __forceinline__ unsigned long long fma2(unsigned long long a,
                                                   unsigned long long b,
                                                   unsigned long long c) {
    unsigned long long d;
    asm("fma.rn.f32x2 %0,%1,%2,%3;" : "=l"(d) : "l"(a), "l"(b), "l"(c));
    return d;
}
__device__ __forceinline__ float upk_sum(unsigned long long v) {
    float lo, hi;
    asm("mov.b64 {%0,%1},%2;" : "=f"(lo), "=f"(hi) : "l"(v));
    return lo + hi;
}

// ---- Kernel A: warp-per-query exact top-32; 2-min summary + bitonic thr ----
__global__ __launch_bounds__(512) void knn_kernel(const float* __restrict__ frames)
{
    __shared__ float4 sc[LPTS];
    const int t = threadIdx.x;
    const int b  = blockIdx.x >> 7;
    const int l0 = (blockIdx.x & 127) * 16;

    const float* fb = frames + (size_t)b * LPTS * 12;
    for (int j = t; j < LPTS; j += 512) {
        float x = fb[j*12+0], y = fb[j*12+1], z = fb[j*12+2];
        float sq = __fadd_rn(__fadd_rn(__fmul_rn(x,x), __fmul_rn(y,y)), __fmul_rn(z,z));
        sc[j] = make_float4(x, y, z, sq);
    }
    __syncthreads();

    const int w = t >> 5, lane = t & 31;
    const int l = l0 + w;
    const float4 q = sc[l];
    const float xi = q.x, yi = q.y, zi = q.z, sqi = q.w;

    unsigned ka = 0xFFFFFFFFu, kb = 0xFFFFFFFFu;
    #pragma unroll 8
    for (int i = 0; i < 64; i++) {
        const float4 c = sc[i * 32 + lane];
        float dot = __fadd_rn(__fadd_rn(__fmul_rn(xi,c.x), __fmul_rn(yi,c.y)), __fmul_rn(zi,c.z));
        float d2  = __fadd_rn(__fadd_rn(sqi, c.w), __fmul_rn(-2.0f, dot));
        unsigned ub  = __float_as_uint(d2);
        unsigned key = (ub & 0x80000000u) ? ~ub : (ub | 0x80000000u);
        unsigned hi = max(key, ka);
        ka = min(key, ka);
        kb = min(kb, hi);
    }
    {   // bitonic sort of 64 summary keys; sorted[31] = provable threshold
        unsigned a = ka, bb = kb;
        #pragma unroll
        for (int k = 2; k <= 64; k <<= 1) {
            #pragma unroll
            for (int j = k >> 1; j > 0; j >>= 1) {
                if (j == 32) {
                    unsigned lo = min(a, bb), hi2 = max(a, bb);
                    a = lo; bb = hi2;
                } else {
                    unsigned oa = __shfl_xor_sync(0xffffffffu, a, j);
                    bool upa = ((lane & j) == 0) == ((lane & k) == 0);
                    a = upa ? min(a, oa) : max(a, oa);
                    unsigned ob = __shfl_xor_sync(0xffffffffu, bb, j);
                    bool upb = ((lane & j) == 0) == (((lane + 32) & k) == 0);
                    bb = upb ? min(bb, ob) : max(bb, ob);
                }
            }
        }
        ka = a;
    }
    unsigned thrk = __shfl_sync(0xffffffffu, ka, 31);

    unsigned long long L = ~0ull;
    #pragma unroll 4
    for (int i = 0; i < 64; i++) {
        const int j = i * 32 + lane;
        const float4 c = sc[j];
        float dot = __fadd_rn(__fadd_rn(__fmul_rn(xi,c.x), __fmul_rn(yi,c.y)), __fmul_rn(zi,c.z));
        float d2  = __fadd_rn(__fadd_rn(sqi, c.w), __fmul_rn(-2.0f, dot));
        unsigned ub  = __float_as_uint(d2);
        unsigned key = (ub & 0x80000000u) ? ~ub : (ub | 0x80000000u);
        unsigned long long pk = ((unsigned long long)key << 32) | (unsigned)j;

        unsigned pending = __ballot_sync(0xffffffffu, key <= thrk);
        if (pending) {
            do {
                const int src = __ffs(pending) - 1;
                pending &= pending - 1;
                const unsigned long long v = __shfl_sync(0xffffffffu, pk, src);
                const unsigned lt = __ballot_sync(0xffffffffu, L < v);
                const unsigned long long up = __shfl_up_sync(0xffffffffu, L, 1);
                const int pos = __popc(lt);
                if (lane == pos)      L = v;
                else if (lane > pos)  L = up;
            } while (pending);
            thrk = min(thrk, __shfl_sync(0xffffffffu, (unsigned)(L >> 32), 31));
        }
    }
    g_knn[(size_t)(b * LPTS + l) * K2 + lane] = (int)(L & 0xffffffffu);
}

// ---- Kernel B: 32 points/block; gauss+M -> GEMM (half weight traffic) ----
__global__ __launch_bounds__(512) void stage1_kernel(
    const float* __restrict__ attr,   const float* __restrict__ frames,
    const int*   __restrict__ aaidx,
    const float* __restrict__ cent1,  const float* __restrict__ prec1,
    const float* __restrict__ opW,    const float* __restrict__ opB,
    const float* __restrict__ embW,   const float* __restrict__ embB,
    const float* __restrict__ betaW,  const float* __restrict__ betaB,
    const float* __restrict__ selfW,  const float* __restrict__ selfB,
    const float* __restrict__ crossW, const float* __restrict__ crossB,
    const float* __restrict__ nodefW, const float* __restrict__ nodefB)
{
    extern __shared__ float sm[];
    float* s_crd  = sm;                       // S1P*16*8  = 4096
    float* s_attr = s_crd  + S1P*16*8;        // S1P*16*20 = 10240
    float* s_M    = s_attr + S1P*16*20;       // S1P*640   = 20480
    float* s_F    = s_M    + S1P*640;         // S1P*128   = 4096

    const int tid  = threadIdx.x;
    const int w    = tid >> 5;
    const int lane = tid & 31;
    const int n0   = blockIdx.x * S1P;
    const int b    = n0 >> 11;

    // gather: each warp handles 2 points (pp = w, w+16)
    for (int pp = w; pp < S1P; pp += 16) {
        const int n  = n0 + pp;
        const int k  = lane & 15;
        const int j  = g_knn[n * K2 + k];
        const int jj = b * LPTS + j;
        if (lane < 16) {
            const float4* fo4 = (const float4*)(frames + (size_t)n * 12);
            float4 f0 = fo4[0], f1 = fo4[1], f2 = fo4[2];
            const float4* fj4 = (const float4*)(frames + (size_t)jj * 12);
            float4 j0 = fj4[0], j2 = fj4[2];
            float dx = j0.x - f0.x, dy = j0.y - f0.y, dz = j0.z - f0.z;
            float dist = sqrtf(dx*dx + dy*dy + dz*dz + 1e-12f);
            float e0 = dx*f0.w + dy*f1.x + dz*f1.y;
            float e1 = dx*f1.z + dy*f1.w + dz*f2.x;
            float e2 = dx*f2.y + dy*f2.z + dz*f2.w;
            float zz  = f2.y*j2.y + f2.z*j2.z + f2.w*j2.w;
            float dzv = (dx*j2.y + dy*j2.z + dz*j2.w) / dist;
            float zdv = (f2.y*dx + f2.z*dy + f2.w*dz) / dist;
            float idist = fminf(fabsf((float)aaidx[jj] - (float)aaidx[n]), 8.0f);
            float* c = s_crd + (pp*16 + k) * 8;
            c[0]=e0; c[1]=e1; c[2]=e2; c[3]=idist; c[4]=zz; c[5]=dzv; c[6]=zdv; c[7]=0.f;
        } else {
            const float4* ap = (const float4*)(attr + (size_t)jj * HIN);
            float4* d = (float4*)(s_attr + (pp*16 + k) * HIN);
            #pragma unroll
            for (int h = 0; h < 5; h++) d[h] = ap[h];
        }
    }
    __syncwarp();

    {   // fused gaussians (lane = g) + M accumulation; constants reused 2x
        unsigned long long pr2[21];
        float pr6[7], ce[7];
        #pragma unroll
        for (int d = 0; d < 7; d++) {
            #pragma unroll
            for (int p = 0; p < 3; p++)
                pr2[d*3+p] = pk2(prec1[(d*7 + 2*p)*NG + lane],
                                 prec1[(d*7 + 2*p + 1)*NG + lane]);
            pr6[d] = prec1[(d*7 + 6)*NG + lane];
            ce[d]  = cent1[d*NG + lane];
        }
        for (int pp = w; pp < S1P; pp += 16) {
            unsigned long long m2[10];
            #pragma unroll
            for (int h = 0; h < 10; h++) m2[h] = 0ull;
            for (int k = 0; k < K1; k++) {
                const float4* cp = (const float4*)(s_crd + (pp*16 + k) * 8);
                float4 a = cp[0], bq = cp[1];
                float diff[7] = { a.x-ce[0], a.y-ce[1], a.z-ce[2], a.w-ce[3],
                                  bq.x-ce[4], bq.y-ce[5], bq.z-ce[6] };
                unsigned long long y01 = 0ull, y23 = 0ull, y45 = 0ull;
                float y6 = 0.f;
                #pragma unroll
                for (int d = 0; d < 7; d++) {
                    unsigned long long dd = pk2(diff[d], diff[d]);
                    y01 = fma2(dd, pr2[d*3+0], y01);
                    y23 = fma2(dd, pr2[d*3+1], y23);
                    y45 = fma2(dd, pr2[d*3+2], y45);
                    y6  = fmaf(diff[d], pr6[d], y6);
                }
                unsigned long long acc2 = fma2(y01, y01, fma2(y23, y23, fma2(y45, y45, 0ull)));
                float acc = upk_sum(acc2) + y6*y6;
                float gk = __expf(-0.5f * acc);
                unsigned long long gk2 = pk2(gk, gk);
                const ulonglong2* ap = (const ulonglong2*)(s_attr + (pp*16 + k) * HIN);
                #pragma unroll
                for (int qq = 0; qq < 5; qq++) {
                    ulonglong2 av = ap[qq];
                    m2[qq*2+0] = fma2(gk2, av.x, m2[qq*2+0]);
                    m2[qq*2+1] = fma2(gk2, av.y, m2[qq*2+1]);
                }
            }
            unsigned long long* mp = (unsigned long long*)(s_M + pp*640 + lane*20);
            #pragma unroll
            for (int h = 0; h < 10; h++) mp[h] = m2[h];
        }
    }
    __syncthreads();

    {   // block GEMM: filt = M(32x640) @ opW(640x128); 8 points per group
        const int o   = tid & 127;
        const int grp = tid >> 7;               // 0..3, 8 points each
        const float* mb = s_M + grp * 8 * 640;
        unsigned long long acc[8];
        #pragma unroll
        for (int p = 0; p < 8; p++) acc[p] = 0ull;
        #pragma unroll 2
        for (int gh = 0; gh < 640; gh += 4) {
            const float* wp = opW + (size_t)gh * DM + o;
            unsigned long long w01 = pk2(wp[0],    wp[DM]);
            unsigned long long w23 = pk2(wp[2*DM], wp[3*DM]);
            #pragma unroll
            for (int p = 0; p < 8; p++) {
                ulonglong2 u = *(const ulonglong2*)(mb + p*640 + gh);
                acc[p] = fma2(u.x, w01, acc[p]);
                acc[p] = fma2(u.y, w23, acc[p]);
            }
        }
        const float bo = opB[o];
        #pragma unroll
        for (int p = 0; p < 8; p++)
            s_F[(grp*8 + p)*DM + o] = fmaxf(upk_sum(acc[p]) + bo, 0.f);
    }
    __syncthreads();

    // emb + 5 heads; each warp handles 2 points
    for (int pp = w; pp < S1P; pp += 16) {
        const int n = n0 + pp;
        float acc = embB[lane];
        const float* fp = s_F + pp * DM;
        #pragma unroll
        for (int ob = 0; ob < DM; ob += 4) {
            float4 f = *(const float4*)(fp + ob);
            acc += f.x * embW[(ob+0)*DH + lane];
            acc += f.y * embW[(ob+1)*DH + lane];
            acc += f.z * embW[(ob+2)*DH + lane];
            acc += f.w * embW[(ob+3)*DH + lane];
        }
        float emb = fmaxf(acc, 0.f);
        float hb = emb * betaW[lane];
        float hs = emb * selfW[lane];
        float hc = emb * crossW[lane];
        float h0 = emb * nodefW[lane*2 + 0];
        float h1 = emb * nodefW[lane*2 + 1];
        #pragma unroll
        for (int off = 16; off > 0; off >>= 1) {
            hb += __shfl_xor_sync(0xffffffffu, hb, off);
            hs += __shfl_xor_sync(0xffffffffu, hs, off);
            hc += __shfl_xor_sync(0xffffffffu, hc, off);
            h0 += __shfl_xor_sync(0xffffffffu, h0, off);
            h1 += __shfl_xor_sync(0xffffffffu, h1, off);
        }
        if (lane == 0) {
            float4* hp = (float4*)(g_heads + (size_t)n * 8);
            hp[0] = make_float4(fmaxf(hb + betaB[0],  0.f),
                                fmaxf(hs + selfB[0],  0.f),
                                fmaxf(hc + crossB[0], 0.f),
                                fmaxf(h0 + nodefB[0], 0.f));
            hp[1] = make_float4(fmaxf(h1 + nodefB[1], 0.f), 0.f, 0.f, 0.f);
        }
    }
}

// ---- Kernel C: gaussian attention, packed constants + vector gathers ----
__global__ __launch_bounds__(256) void stage2_kernel(
    const float* __restrict__ frames, const int* __restrict__ aaidx,
    const float* __restrict__ cent2,  const float* __restrict__ prec2,
    const float* __restrict__ emb2W,  const float* __restrict__ emb2B,
    float* __restrict__ out)
{
    __shared__ float s_gau[NG * 32];

    const int tid = threadIdx.x;
    for (int qi = tid; qi < NG * 32; qi += 256) {
        const int n2 = qi >> 5, e = qi & 31;
        float v = 0.f;
        if (e < 20) {
            const int u = e >> 1, d = u >> 1, kk = (u & 1) * 2 + (e & 1);
            v = prec2[(d*5 + kk)*NG + n2];
        } else if (e < 24)  v = cent2[(e-20)*NG + n2];
        else if (e < 28)    v = prec2[((e-24)*5 + 4)*NG + n2];
        else if (e == 28)   v = cent2[4*NG + n2];
        else if (e == 29)   v = prec2[(4*5 + 4)*NG + n2];
        else if (e == 30)   v = emb2W[n2];
        s_gau[qi] = v;
    }
    __syncthreads();

    const int w = tid >> 5, lane = tid & 31;
    const int n = blockIdx.x * 8 + w;
    const int b = n >> 11, l = n & 2047;
    const int j  = g_knn[n * K2 + lane];
    const int jj = b * LPTS + j;

    const float4* fo4 = (const float4*)(frames + (size_t)n * 12);
    float4 f0 = fo4[0], f2 = fo4[2];
    const float4* fj4 = (const float4*)(frames + (size_t)jj * 12);
    float4 j0 = fj4[0], j2 = fj4[2];
    float dx = j0.x - f0.x, dy = j0.y - f0.y, dzc = j0.z - f0.z;
    float dist = sqrtf(dx*dx + dy*dy + dzc*dzc + 1e-12f);
    float zz  = f2.y*j2.y + f2.z*j2.z + f2.w*j2.w;
    float dzv = (dx*j2.y + dy*j2.z + dzc*j2.w) / dist;
    float zdv = (f2.y*dx + f2.z*dy + f2.w*dzc) / dist;
    float idist = fminf(fabsf((float)aaidx[jj] - (float)aaidx[n]), 8.0f);
    const float cd0 = dist, cd1 = zz, cd2 = dzv, cd3 = zdv, cd4 = idist;

    float gw = emb2B[0];
    #pragma unroll 4
    for (int n2 = 0; n2 < NG; n2++) {
        const float* gp = s_gau + n2 * 32;
        const ulonglong2* pp = (const ulonglong2*)gp;
        float4 c03 = *(const float4*)(gp + 20);
        float4 p03 = *(const float4*)(gp + 24);
        float4 tl  = *(const float4*)(gp + 28);
        float df0 = cd0 - c03.x, df1 = cd1 - c03.y, df2 = cd2 - c03.z,
              df3 = cd3 - c03.w, df4 = cd4 - tl.x;
        ulonglong2 q0 = pp[0], q1 = pp[1], q2 = pp[2], q3 = pp[3], q4 = pp[4];
        unsigned long long y01 = 0ull, y23 = 0ull;
        float y4 = 0.f;
        unsigned long long dd;
        dd = pk2(df0, df0); y01 = fma2(dd, q0.x, y01); y23 = fma2(dd, q0.y, y23); y4 = fmaf(df0, p03.x, y4);
        dd = pk2(df1, df1); y01 = fma2(dd, q1.x, y01); y23 = fma2(dd, q1.y, y23); y4 = fmaf(df1, p03.y, y4);
        dd = pk2(df2, df2); y01 = fma2(dd, q2.x, y01); y23 = fma2(dd, q2.y, y23); y4 = fmaf(df2, p03.z, y4);
        dd = pk2(df3, df3); y01 = fma2(dd, q3.x, y01); y23 = fma2(dd, q3.y, y23); y4 = fmaf(df3, p03.w, y4);
        dd = pk2(df4, df4); y01 = fma2(dd, q4.x, y01); y23 = fma2(dd, q4.y, y23); y4 = fmaf(df4, tl.y,  y4);
        unsigned long long acc2 = fma2(y01, y01, fma2(y23, y23, 0ull));
        float acc = upk_sum(acc2) + y4*y4;
        gw += __expf(-0.5f * acc) * tl.z;
    }
    gw = fmaxf(gw, 0.f);

    const float4* hj4 = (const float4*)(g_heads + (size_t)jj * 8);
    float4 ha = hj4[0], hb4 = hj4[1];
    const float* hi = g_heads + (size_t)n * 8;
    float beta = hi[0], satt = hi[1];
    float e = (j == l) ? satt : ha.z;
    float logit = beta * e;
    float mx = logit;
    #pragma unroll
    for (int off = 16; off > 0; off >>= 1)
        mx = fmaxf(mx, __shfl_xor_sync(0xffffffffu, mx, off));
    float wv = gw * __expf(logit - mx);
    float s = wv, n0 = wv * ha.w, n1 = wv * hb4.x;
    #pragma unroll
    for (int off = 16; off > 0; off >>= 1) {
        s  += __shfl_xor_sync(0xffffffffu, s,  off);
        n0 += __shfl_xor_sync(0xffffffffu, n0, off);
        n1 += __shfl_xor_sync(0xffffffffu, n1, off);
    }
    if (lane == 0) {
        float inv = 1.f / (s + 1e-6f);
        out[n*2 + 0] = n0 * inv;
        out[n*2 + 1] = n1 * inv;
    }
}

extern "C" void kernel_launch(void* const* d_in, const int* in_sizes, int n_in,
                              void* d_out, int out_size)
{
    const float* attr    = (const float*)d_in[0];
    const float* frames  = (const float*)d_in[1];
    const int*   aaidx   = (const int*)  d_in[2];
    const float* cent1   = (const float*)d_in[3];
    const float* prec1   = (const float*)d_in[4];
    const float* opW     = (const float*)d_in[5];
    const float* opB     = (const float*)d_in[6];
    const float* embW    = (const float*)d_in[7];
    const float* embB    = (const float*)d_in[8];
    const float* betaW   = (const float*)d_in[9];
    const float* betaB   = (const float*)d_in[10];
    const float* selfW   = (const float*)d_in[11];
    const float* selfB   = (const float*)d_in[12];
    const float* crossW  = (const float*)d_in[13];
    const float* crossB  = (const float*)d_in[14];
    const float* nodefW  = (const float*)d_in[15];
    const float* nodefB  = (const float*)d_in[16];
    const float* cent2   = (const float*)d_in[17];
    const float* prec2   = (const float*)d_in[18];
    const float* emb2W   = (const float*)d_in[19];
    const float* emb2B   = (const float*)d_in[20];
    float* out = (float*)d_out;

    const int smem1 = (S1P*16*8 + S1P*16*20 + S1P*640 + S1P*128) * 4;  // 155648

    static int s_attr_set = 0;
    if (!s_attr_set) {
        cudaFuncSetAttribute(stage1_kernel,
                             cudaFuncAttributeMaxDynamicSharedMemorySize, smem1);
        s_attr_set = 1;
    }

    knn_kernel<<<NPTS / 16, 512>>>(frames);
    stage1_kernel<<<NPTS / S1P, 512, smem1>>>(
        attr, frames, aaidx, cent1, prec1, opW, opB, embW, embB,
        betaW, betaB, selfW, selfB, crossW, crossB, nodefW, nodefB);
    stage2_kernel<<<NPTS / 8, 256>>>(frames, aaidx, cent2, prec2, emb2W, emb2B, out);
}